// round 15
// baseline (speedup 1.0000x reference)
#include <cuda_runtime.h>
#include <cuda_fp16.h>
#include <cstdint>

// ============================================================
// MADE/IAF flow step on tensor cores via mma.sync (fp16 HMMA, f32 acc).
// Single-pass fp16 (rel_err ~4.4e-4, under the 1e-3 gate).
// + MADE-mask block sparsity (exact k-chunk skipping, chunk=32).
// R15: GEMM1 = byte-exact R12 best kernel. GEMM2 fused with the finish
//      epilogue: each CTA computes the mu-tile (cols d) AND the paired
//      ls-tile (cols d+1024; identical mask/kept-list), then writes
//      out[r, perm[d]] = z*exp(ls)+mu directly + atomic log_det sums.
//      g_res and finish_kernel eliminated.
// GEMM1: h = relu(zp @ (W1*M1) + b1)   [4096,1024]x[1024,4096]
// GEMM2: res = h @ (W2*M2) + b2 -> fused epilogue
// ============================================================

// ---------------- device scratch (no allocs allowed) ----------------
__device__ __half g_zh[4096ull * 1024ull];    // [B,D] fp16
__device__ __half g_w1h[4096ull * 1024ull];   // [N=4096,K=1024]
__device__ __half g_hh[4096ull * 4096ull];    // [B,H] fp16
__device__ __half g_w2h[2048ull * 4096ull];   // [N=2048,K=4096]

// ---------------- PTX helpers (all baseline sm_80+ PTX) ----------------
__device__ __forceinline__ uint32_t smem_u32(const void* p) {
    uint32_t a;
    asm("{ .reg .u64 t; cvta.to.shared.u64 t, %1; cvt.u32.u64 %0, t; }" : "=r"(a) : "l"(p));
    return a;
}
__device__ __forceinline__ void cp16(uint32_t s, const void* g) {
    asm volatile("cp.async.cg.shared.global [%0], [%1], 16;" :: "r"(s), "l"(g));
}
__device__ __forceinline__ void cp_commit() {
    asm volatile("cp.async.commit_group;" ::: "memory");
}
__device__ __forceinline__ void cp_wait1() {
    asm volatile("cp.async.wait_group 1;" ::: "memory");
}
__device__ __forceinline__ void ldm_x4(uint32_t addr, uint32_t* r) {
    asm volatile("ldmatrix.sync.aligned.m8n8.x4.shared.b16 {%0,%1,%2,%3}, [%4];"
                 : "=r"(r[0]), "=r"(r[1]), "=r"(r[2]), "=r"(r[3]) : "r"(addr));
}
__device__ __forceinline__ void mma16816(float* c, const uint32_t* a, const uint32_t* b) {
    asm volatile(
        "mma.sync.aligned.m16n8k16.row.col.f32.f16.f16.f32 "
        "{%0,%1,%2,%3}, {%4,%5,%6,%7}, {%8,%9}, {%0,%1,%2,%3};"
        : "+f"(c[0]), "+f"(c[1]), "+f"(c[2]), "+f"(c[3])
        : "r"(a[0]), "r"(a[1]), "r"(a[2]), "r"(a[3]), "r"(b[0]), "r"(b[1]));
}

// ---------------- prep kernels ----------------
// zero the poisoned log_det region of d_out before gemm2's atomics
__global__ void init_logdet(float* __restrict__ out, size_t off, int Bn) {
    int i = blockIdx.x * blockDim.x + threadIdx.x;
    if (i < Bn) out[off + i] = 0.f;
}

__global__ void split_z_kernel(const float* __restrict__ z, const int* __restrict__ perm,
                               int D, long total) {
    long idx = (long)blockIdx.x * blockDim.x + threadIdx.x;
    if (idx >= total) return;
    int i = (int)(idx >> 10);      // D = 1024
    int k = (int)(idx & 1023);
    g_zh[idx] = __float2half(z[(size_t)i * D + perm[k]]);
}

// Merged mask+transpose to fp16 for BOTH weights in one launch.
// W [K,N] fp32 -> out [N,K] fp16, 64x64 tiles.
// mode 1: mask = (n % 1023) >= k          (W1/M1)
// mode 2: mask = (n % 1024) > (k % 1023)  (W2/M2)
__global__ __launch_bounds__(256) void prep_w_all(
    const float* __restrict__ W1, const float* __restrict__ W2,
    __half* __restrict__ o1, __half* __restrict__ o2,
    int D, int H, int N2) {
    __shared__ float tile[64][65];
    const int nblk1 = (H / 64) * (D / 64);
    const int b = blockIdx.x;
    const float* W;
    __half* oH;
    int K, N, mode, tix;
    if (b < nblk1) { W = W1; oH = o1; K = D; N = H;  mode = 1; tix = b; }
    else           { W = W2; oH = o2; K = H; N = N2; mode = 2; tix = b - nblk1; }
    const int nx = N / 64;
    const int n0 = (tix % nx) * 64;
    const int k0 = (tix / nx) * 64;
    const int tid = threadIdx.x;
#pragma unroll
    for (int it = 0; it < 4; it++) {
        int lin = tid + it * 256;
        int k = lin >> 4;
        int n4 = (lin & 15) << 2;
        float4 v = *reinterpret_cast<const float4*>(&W[(size_t)(k0 + k) * N + n0 + n4]);
        tile[k][n4 + 0] = v.x;
        tile[k][n4 + 1] = v.y;
        tile[k][n4 + 2] = v.z;
        tile[k][n4 + 3] = v.w;
    }
    __syncthreads();
    const int tn = tid & 63;
    const int kg = tid >> 6;
    const int n  = n0 + tn;
    const int jm = (mode == 1) ? (n % 1023) : (n & 1023);
    uint32_t hibuf[8];
#pragma unroll
    for (int e = 0; e < 8; e++) {
        float v0, v1;
        {
            int k = k0 + kg * 16 + 2 * e;
            float v = tile[kg * 16 + 2 * e][tn];
            bool m = (mode == 1) ? (jm >= k) : (jm > (k % 1023));
            v0 = m ? v : 0.f;
        }
        {
            int k = k0 + kg * 16 + 2 * e + 1;
            float v = tile[kg * 16 + 2 * e + 1][tn];
            bool m = (mode == 1) ? (jm >= k) : (jm > (k % 1023));
            v1 = m ? v : 0.f;
        }
        __half2 ph; ph.x = __float2half(v0); ph.y = __float2half(v1);
        hibuf[e] = *reinterpret_cast<uint32_t*>(&ph);
    }
    const size_t ob = (size_t)n * K + k0 + kg * 16;
    *reinterpret_cast<uint4*>(oH + ob)     = *reinterpret_cast<uint4*>(hibuf);
    *reinterpret_cast<uint4*>(oH + ob + 8) = *reinterpret_cast<uint4*>(hibuf + 4);
}

// ---------------- GEMM1 (byte-exact R12 best: 128 thr, warp 64x64) ----------------
#define SA_BYTES   16384
#define STG_BYTES  32768
#define SM1_TOTAL  (3 * STG_BYTES + 1024)
#define NTHR1      128

__global__ __launch_bounds__(NTHR1) void gemm1_kernel(
    const __half* __restrict__ Ah, const __half* __restrict__ Bh,
    const float* __restrict__ bias, int K, int Nout,
    __half* __restrict__ outH)
{
    extern __shared__ char smem[];
    const uint32_t sb = smem_u32(smem);
    int* kt = (int*)(smem + 3 * STG_BYTES);
    const int tid  = threadIdx.x;
    const int lane = tid & 31;
    const int w    = tid >> 5;
    const int wm   = w & 1;        // 2 warps in M
    const int wn   = w >> 1;       // 2 warps in N
    const int row0 = blockIdx.y * 128;
    const int col0 = blockIdx.x * 128;
    const int nk   = K >> 5;

    if (tid == 0) {
        int c = 0;
        for (int t = 0; t < nk; t++) {
            const int k0 = t << 5;
            int c0 = col0 % 1023;
            int jmmax = (c0 + 127 > 1022) ? 1022 : (c0 + 127);
            if (k0 <= jmmax) kt[c++] = t;
        }
        kt[255] = c;
    }
    __syncthreads();
    const int cnt = kt[255];

    float acc[4][8][4];
#pragma unroll
    for (int mt = 0; mt < 4; mt++)
#pragma unroll
        for (int nt = 0; nt < 8; nt++)
#pragma unroll
            for (int e = 0; e < 4; e++) acc[mt][nt][e] = 0.f;

    auto load_stage = [&](int chunk, int slot) {
        const int k0 = chunk << 5;
        const uint32_t s0 = sb + slot * STG_BYTES;
#pragma unroll
        for (int i = 0; i < 4; i++) {
            int idx = tid + i * NTHR1;
            int row = idx >> 2, cc = idx & 3;
            const __half* src = Ah + (size_t)(row0 + row) * K + k0 + cc * 8;
            cp16(s0 + row * 128 + ((cc * 16) ^ ((row & 7) << 4)), src);
        }
#pragma unroll
        for (int i = 0; i < 4; i++) {
            int idx = tid + i * NTHR1;
            int row = idx >> 2, cc = idx & 3;
            const __half* src = Bh + (size_t)(col0 + row) * K + k0 + cc * 8;
            cp16(s0 + SA_BYTES + row * 128 + ((cc * 16) ^ ((row & 7) << 4)), src);
        }
    };

    load_stage(kt[0], 0);
    cp_commit();
    if (cnt > 1) load_stage(kt[1], 1);
    cp_commit();

    int rA[4], xA[4];
#pragma unroll
    for (int mt = 0; mt < 4; mt++) {
        int r = wm * 64 + mt * 16 + (lane & 15);
        rA[mt] = r * 128;
        xA[mt] = (r & 7) << 4;
    }
    const int kA2 = (lane >> 4) << 4;
    int rB[4], xB[4];
#pragma unroll
    for (int p = 0; p < 4; p++) {
        int r = wn * 64 + p * 16 + (lane & 7) + ((lane & 16) >> 1);
        rB[p] = r * 128;
        xB[p] = (r & 7) << 4;
    }
    const int kB2 = (lane & 8) << 1;

    for (int i = 0; i < cnt; i++) {
        cp_wait1();
        __syncthreads();
        if (i + 2 < cnt) load_stage(kt[i + 2], (i + 2) % 3);
        cp_commit();

        const uint32_t sA = sb + (i % 3) * STG_BYTES;
        const uint32_t sB = sA + SA_BYTES;
#pragma unroll
        for (int ks = 0; ks < 2; ks++) {
            const int kbA = ks * 32 + kA2;
            const int kbB = ks * 32 + kB2;
            uint32_t Af[4][4], bh[4][4];
#pragma unroll
            for (int mt = 0; mt < 4; mt++)
                ldm_x4(sA + rA[mt] + (kbA ^ xA[mt]), Af[mt]);
#pragma unroll
            for (int p = 0; p < 4; p++)
                ldm_x4(sB + rB[p] + (kbB ^ xB[p]), bh[p]);
#pragma unroll
            for (int mt = 0; mt < 4; mt++)
#pragma unroll
                for (int p = 0; p < 4; p++) {
                    mma16816(acc[mt][2 * p + 0], Af[mt], bh[p]);
                    mma16816(acc[mt][2 * p + 1], Af[mt], bh[p] + 2);
                }
        }
    }

    const int mrow = lane >> 2;
    const int mcol = (lane & 3) * 2;
#pragma unroll
    for (int mt = 0; mt < 4; mt++) {
        const int rbase = row0 + wm * 64 + mt * 16 + mrow;
#pragma unroll
        for (int nt = 0; nt < 8; nt++) {
            const int c = col0 + wn * 64 + nt * 8 + mcol;
            const float b0 = bias[c], b1 = bias[c + 1];
#pragma unroll
            for (int h = 0; h < 2; h++) {
                const int r = rbase + h * 8;
                float v0 = fmaxf(acc[mt][nt][2 * h + 0] + b0, 0.f);
                float v1 = fmaxf(acc[mt][nt][2 * h + 1] + b1, 0.f);
                __half2 ph; ph.x = __float2half(v0); ph.y = __float2half(v1);
                *(__half2*)(outH + (size_t)r * Nout + c) = ph;
            }
        }
    }
}

// ---------------- GEMM2 fused with finish ----------------
// Each CTA: A tile [128 x K-chunk], B1 = W2 rows [col0, col0+128) (mu cols),
// B2 = W2 rows [col0+1024, ...) (log_s cols). Same mask/kept-list for both.
// Epilogue: d = global col in [0,1024); j = perm[d];
//   out[r, j] = z[r, j] * exp(ls[r,d]) + mu[r,d];  atomicAdd log_det[r] += ls.
#define SB2_OFF    (SA_BYTES)                 // B1 at +16K, B2 at +32K
#define STG2_BYTES (3 * SA_BYTES)             // 48KB per stage
#define SM2_TOTAL  (3 * STG2_BYTES + 1024)
#define NTHR2      256

__global__ __launch_bounds__(NTHR2) void gemm2_fused(
    const __half* __restrict__ Ah, const __half* __restrict__ Bh,
    const float* __restrict__ bias, const int* __restrict__ perm,
    const float* __restrict__ z, float* __restrict__ out,
    int K, int D, int Bn)
{
    extern __shared__ char smem[];
    const uint32_t sb = smem_u32(smem);
    int* kt = (int*)(smem + 3 * STG2_BYTES);
    const int tid  = threadIdx.x;
    const int lane = tid & 31;
    const int w    = tid >> 5;
    const int wm   = w & 1;        // 2 warps in M
    const int wn   = w >> 1;       // 4 warps in N
    const int row0 = blockIdx.y * 128;
    const int col0 = blockIdx.x * 128;      // d in [0, 1024)
    const int nk   = K >> 5;

    if (tid == 0) {
        int c = 0;
        const int jdmax = col0 + 127;       // mask: keep iff k%1023 < jd for some jd
        for (int t = 0; t < nk; t++) {
            const int k0 = t << 5;
            int km0 = k0 % 1023;
            if (km0 < jdmax || km0 > 991) kt[c++] = t;
        }
        kt[255] = c;
    }
    __syncthreads();
    const int cnt = kt[255];

    float accM[4][4][4], accL[4][4][4];
#pragma unroll
    for (int mt = 0; mt < 4; mt++)
#pragma unroll
        for (int nt = 0; nt < 4; nt++)
#pragma unroll
            for (int e = 0; e < 4; e++) { accM[mt][nt][e] = 0.f; accL[mt][nt][e] = 0.f; }

    auto load_stage = [&](int chunk, int slot) {
        const int k0 = chunk << 5;
        const uint32_t s0 = sb + slot * STG2_BYTES;
        // A: 512 cp16
#pragma unroll
        for (int i = 0; i < 2; i++) {
            int idx = tid + i * NTHR2;
            int row = idx >> 2, cc = idx & 3;
            const __half* src = Ah + (size_t)(row0 + row) * K + k0 + cc * 8;
            cp16(s0 + row * 128 + ((cc * 16) ^ ((row & 7) << 4)), src);
        }
        // B1 (mu cols): 512 cp16
#pragma unroll
        for (int i = 0; i < 2; i++) {
            int idx = tid + i * NTHR2;
            int row = idx >> 2, cc = idx & 3;
            const __half* src = Bh + (size_t)(col0 + row) * K + k0 + cc * 8;
            cp16(s0 + SB2_OFF + row * 128 + ((cc * 16) ^ ((row & 7) << 4)), src);
        }
        // B2 (log_s cols): 512 cp16
#pragma unroll
        for (int i = 0; i < 2; i++) {
            int idx = tid + i * NTHR2;
            int row = idx >> 2, cc = idx & 3;
            const __half* src = Bh + (size_t)(col0 + 1024 + row) * K + k0 + cc * 8;
            cp16(s0 + 2 * SB2_OFF + row * 128 + ((cc * 16) ^ ((row & 7) << 4)), src);
        }
    };

    load_stage(kt[0], 0);
    cp_commit();
    if (cnt > 1) load_stage(kt[1], 1);
    cp_commit();

    int rA[4], xA[4];
#pragma unroll
    for (int mt = 0; mt < 4; mt++) {
        int r = wm * 64 + mt * 16 + (lane & 15);
        rA[mt] = r * 128;
        xA[mt] = (r & 7) << 4;
    }
    const int kA2 = (lane >> 4) << 4;
    int rB[2], xB[2];
#pragma unroll
    for (int p = 0; p < 2; p++) {
        int r = wn * 32 + p * 16 + (lane & 7) + ((lane & 16) >> 1);
        rB[p] = r * 128;
        xB[p] = (r & 7) << 4;
    }
    const int kB2 = (lane & 8) << 1;

    for (int i = 0; i < cnt; i++) {
        cp_wait1();
        __syncthreads();
        if (i + 2 < cnt) load_stage(kt[i + 2], (i + 2) % 3);
        cp_commit();

        const uint32_t sA  = sb + (i % 3) * STG2_BYTES;
        const uint32_t sB1 = sA + SB2_OFF;
        const uint32_t sB2 = sA + 2 * SB2_OFF;
#pragma unroll
        for (int ks = 0; ks < 2; ks++) {
            const int kbA = ks * 32 + kA2;
            const int kbB = ks * 32 + kB2;
            uint32_t Af[4][4], b1f[2][4], b2f[2][4];
#pragma unroll
            for (int mt = 0; mt < 4; mt++)
                ldm_x4(sA + rA[mt] + (kbA ^ xA[mt]), Af[mt]);
#pragma unroll
            for (int p = 0; p < 2; p++) {
                ldm_x4(sB1 + rB[p] + (kbB ^ xB[p]), b1f[p]);
                ldm_x4(sB2 + rB[p] + (kbB ^ xB[p]), b2f[p]);
            }
#pragma unroll
            for (int mt = 0; mt < 4; mt++)
#pragma unroll
                for (int p = 0; p < 2; p++) {
                    mma16816(accM[mt][2 * p + 0], Af[mt], b1f[p]);
                    mma16816(accM[mt][2 * p + 1], Af[mt], b1f[p] + 2);
                    mma16816(accL[mt][2 * p + 0], Af[mt], b2f[p]);
                    mma16816(accL[mt][2 * p + 1], Af[mt], b2f[p] + 2);
                }
        }
    }

    // fused finish epilogue
    const int mrow = lane >> 2;
    const int mcol = (lane & 3) * 2;
    const size_t ld_off = (size_t)Bn * D;
#pragma unroll
    for (int mt = 0; mt < 4; mt++) {
        const int rbase = row0 + wm * 64 + mt * 16 + mrow;
#pragma unroll
        for (int h = 0; h < 2; h++) {
            const int r = rbase + h * 8;
            float rowsum = 0.f;
#pragma unroll
            for (int nt = 0; nt < 4; nt++) {
                const int d = col0 + wn * 32 + nt * 8 + mcol;
                float mu0 = accM[mt][nt][2 * h + 0] + bias[d];
                float mu1 = accM[mt][nt][2 * h + 1] + bias[d + 1];
                float ls0 = accL[mt][nt][2 * h + 0] + bias[1024 + d];
                float ls1 = accL[mt][nt][2 * h + 1] + bias[1024 + d + 1];
                int j0 = perm[d], j1 = perm[d + 1];
                out[(size_t)r * D + j0] = fmaf(z[(size_t)r * D + j0], expf(ls0), mu0);
                out[(size_t)r * D + j1] = fmaf(z[(size_t)r * D + j1], expf(ls1), mu1);
                rowsum += ls0 + ls1;
            }
            atomicAdd(&out[ld_off + r], rowsum);
        }
    }
}

// ---------------- launch ----------------
extern "C" void kernel_launch(void* const* d_in, const int* in_sizes, int n_in,
                              void* d_out, int out_size) {
    const float* z    = (const float*)d_in[0];
    const float* W1   = (const float*)d_in[1];
    const float* b1   = (const float*)d_in[2];
    const float* W2   = (const float*)d_in[3];
    const float* b2   = (const float*)d_in[4];
    const int*   perm = (const int*)d_in[5];

    const int D  = in_sizes[5];      // 1024
    const int H  = in_sizes[2];      // 4096
    const int N2 = in_sizes[4];      // 2048
    const int B  = in_sizes[0] / D;  // 4096

    cudaFuncSetAttribute(gemm1_kernel, cudaFuncAttributeMaxDynamicSharedMemorySize, SM1_TOTAL);
    cudaFuncSetAttribute(gemm2_fused,  cudaFuncAttributeMaxDynamicSharedMemorySize, SM2_TOTAL);

    __half *zh, *w1h, *hh, *w2h;
    cudaGetSymbolAddress((void**)&zh,  g_zh);
    cudaGetSymbolAddress((void**)&w1h, g_w1h);
    cudaGetSymbolAddress((void**)&hh,  g_hh);
    cudaGetSymbolAddress((void**)&w2h, g_w2h);

    float* out = (float*)d_out;

    init_logdet<<<(B + 255) / 256, 256>>>(out, (size_t)B * D, B);
    split_z_kernel<<<(long)B * D / 256, 256>>>(z, perm, D, (long)B * D);
    const int nblk = (H / 64) * (D / 64) + (N2 / 64) * (H / 64);
    prep_w_all<<<nblk, 256>>>(W1, W2, w1h, w2h, D, H, N2);

    // GEMM1: [B,D] x [D,H]^T-packed -> h (fp16)
    gemm1_kernel<<<dim3(H / 128, B / 128), NTHR1, SM1_TOTAL>>>(
        zh, w1h, b1, D, H, hh);
    // GEMM2 fused: [B,H] x paired W2 columns -> out + log_det
    gemm2_fused<<<dim3(D / 128, B / 128), NTHR2, SM2_TOTAL>>>(
        hh, w2h, b2, perm, z, out, H, D, B);
}

// round 16
// speedup vs baseline: 1.1845x; 1.1845x over previous
#include <cuda_runtime.h>
#include <cuda_fp16.h>
#include <cstdint>

// ============================================================
// MADE/IAF flow step on tensor cores via mma.sync (fp16 HMMA, f32 acc).
// Single-pass fp16 (rel_err ~4.4e-4, under the 1e-3 gate).
// + MADE-mask block sparsity (exact k-chunk skipping, chunk=32).
// R16: byte-exact R12 best configuration (268.4us), with build_inv
//      folded into split_z (one fewer launch). GEMM bodies untouched.
// GEMM1: h = relu(zp @ (W1*M1) + b1)   [4096,1024]x[1024,4096]
// GEMM2: res = h @ (W2*M2) + b2        [4096,4096]x[4096,2048]
// finish: out[i,j] = z[i,j]*exp(ls[i,inv[j]]) + mu[i,inv[j]];
//         log_det[i] = sum_j ls[i,inv[j]]
// ============================================================

// ---------------- device scratch (no allocs allowed) ----------------
__device__ float  g_res[4096ull * 2048ull];   // gemm2 out (fp32)
__device__ int    g_inv[4096];
__device__ __half g_zh[4096ull * 1024ull];    // [B,D] fp16
__device__ __half g_w1h[4096ull * 1024ull];   // [N=4096,K=1024]
__device__ __half g_hh[4096ull * 4096ull];    // [B,H] fp16
__device__ __half g_w2h[2048ull * 4096ull];   // [N=2048,K=4096]

// ---------------- PTX helpers (all baseline sm_80+ PTX) ----------------
__device__ __forceinline__ uint32_t smem_u32(const void* p) {
    uint32_t a;
    asm("{ .reg .u64 t; cvta.to.shared.u64 t, %1; cvt.u32.u64 %0, t; }" : "=r"(a) : "l"(p));
    return a;
}
__device__ __forceinline__ void cp16(uint32_t s, const void* g) {
    asm volatile("cp.async.cg.shared.global [%0], [%1], 16;" :: "r"(s), "l"(g));
}
__device__ __forceinline__ void cp_commit() {
    asm volatile("cp.async.commit_group;" ::: "memory");
}
__device__ __forceinline__ void cp_wait1() {
    asm volatile("cp.async.wait_group 1;" ::: "memory");
}
__device__ __forceinline__ void ldm_x4(uint32_t addr, uint32_t* r) {
    asm volatile("ldmatrix.sync.aligned.m8n8.x4.shared.b16 {%0,%1,%2,%3}, [%4];"
                 : "=r"(r[0]), "=r"(r[1]), "=r"(r[2]), "=r"(r[3]) : "r"(addr));
}
__device__ __forceinline__ void mma16816(float* c, const uint32_t* a, const uint32_t* b) {
    asm volatile(
        "mma.sync.aligned.m16n8k16.row.col.f32.f16.f16.f32 "
        "{%0,%1,%2,%3}, {%4,%5,%6,%7}, {%8,%9}, {%0,%1,%2,%3};"
        : "+f"(c[0]), "+f"(c[1]), "+f"(c[2]), "+f"(c[3])
        : "r"(a[0]), "r"(a[1]), "r"(a[2]), "r"(a[3]), "r"(b[0]), "r"(b[1]));
}

// ---------------- prep kernels ----------------
// split z (permuted gather) to fp16; first D threads also build inv(perm).
__global__ void split_z_kernel(const float* __restrict__ z, const int* __restrict__ perm,
                               int D, long total) {
    long idx = (long)blockIdx.x * blockDim.x + threadIdx.x;
    if (idx >= total) return;
    if (idx < D) g_inv[perm[idx]] = (int)idx;
    int i = (int)(idx >> 10);      // D = 1024
    int k = (int)(idx & 1023);
    g_zh[idx] = __float2half(z[(size_t)i * D + perm[k]]);
}

// Merged mask+transpose to fp16 for BOTH weights in one launch.
// W [K,N] fp32 -> out [N,K] fp16, 64x64 tiles.
// mode 1: mask = (n % 1023) >= k          (W1/M1)
// mode 2: mask = (n % 1024) > (k % 1023)  (W2/M2)
__global__ __launch_bounds__(256) void prep_w_all(
    const float* __restrict__ W1, const float* __restrict__ W2,
    __half* __restrict__ o1, __half* __restrict__ o2,
    int D, int H, int N2) {
    __shared__ float tile[64][65];
    const int nblk1 = (H / 64) * (D / 64);
    const int b = blockIdx.x;
    const float* W;
    __half* oH;
    int K, N, mode, tix;
    if (b < nblk1) { W = W1; oH = o1; K = D; N = H;  mode = 1; tix = b; }
    else           { W = W2; oH = o2; K = H; N = N2; mode = 2; tix = b - nblk1; }
    const int nx = N / 64;
    const int n0 = (tix % nx) * 64;
    const int k0 = (tix / nx) * 64;
    const int tid = threadIdx.x;
#pragma unroll
    for (int it = 0; it < 4; it++) {
        int lin = tid + it * 256;
        int k = lin >> 4;
        int n4 = (lin & 15) << 2;
        float4 v = *reinterpret_cast<const float4*>(&W[(size_t)(k0 + k) * N + n0 + n4]);
        tile[k][n4 + 0] = v.x;
        tile[k][n4 + 1] = v.y;
        tile[k][n4 + 2] = v.z;
        tile[k][n4 + 3] = v.w;
    }
    __syncthreads();
    const int tn = tid & 63;
    const int kg = tid >> 6;
    const int n  = n0 + tn;
    const int jm = (mode == 1) ? (n % 1023) : (n & 1023);
    uint32_t hibuf[8];
#pragma unroll
    for (int e = 0; e < 8; e++) {
        float v0, v1;
        {
            int k = k0 + kg * 16 + 2 * e;
            float v = tile[kg * 16 + 2 * e][tn];
            bool m = (mode == 1) ? (jm >= k) : (jm > (k % 1023));
            v0 = m ? v : 0.f;
        }
        {
            int k = k0 + kg * 16 + 2 * e + 1;
            float v = tile[kg * 16 + 2 * e + 1][tn];
            bool m = (mode == 1) ? (jm >= k) : (jm > (k % 1023));
            v1 = m ? v : 0.f;
        }
        __half2 ph; ph.x = __float2half(v0); ph.y = __float2half(v1);
        hibuf[e] = *reinterpret_cast<uint32_t*>(&ph);
    }
    const size_t ob = (size_t)n * K + k0 + kg * 16;
    *reinterpret_cast<uint4*>(oH + ob)     = *reinterpret_cast<uint4*>(hibuf);
    *reinterpret_cast<uint4*>(oH + ob + 8) = *reinterpret_cast<uint4*>(hibuf + 4);
}

// ---------------- mma.sync GEMM (single fp16, chunk skipping) ----------------
// C[m,n] = sum_k A[m,k]*B[n,k]; A [M,K] fp16, B [N,K] fp16.
// CTA tile 128x128, K-chunk 32, 4 warps (2x2), warp tile 64x64, 3-stage cp.async,
// 2 CTAs/SM. Smem rows 128B XOR-swizzled: byte = row*128 + (inner ^ ((row&7)<<4));
// only the k<64-byte (hi) slots of each row are used (A and B identical layout).
#define SA_BYTES   16384
#define STG_BYTES  32768
#define SM_TOTAL   (3 * STG_BYTES + 1024)
#define NTHR       128

template <int MODE>
__global__ __launch_bounds__(NTHR) void gemm_mma(
    const __half* __restrict__ Ah, const __half* __restrict__ Bh,
    const float* __restrict__ bias, int K, int Nout,
    float* __restrict__ outF, __half* __restrict__ outH)
{
    extern __shared__ char smem[];
    const uint32_t sb = smem_u32(smem);
    int* kt = (int*)(smem + 3 * STG_BYTES);
    const int tid  = threadIdx.x;
    const int lane = tid & 31;
    const int w    = tid >> 5;
    const int wm   = w & 1;        // 2 warps in M
    const int wn   = w >> 1;       // 2 warps in N
    const int row0 = blockIdx.y * 128;
    const int col0 = blockIdx.x * 128;
    const int nk   = K >> 5;

    // ---- build kept-chunk list (mask-induced block sparsity) ----
    if (tid == 0) {
        int c = 0;
        for (int t = 0; t < nk; t++) {
            const int k0 = t << 5;
            bool keep;
            if (MODE == 1) {
                int c0 = col0 % 1023;
                int jmmax = (c0 + 127 > 1022) ? 1022 : (c0 + 127);
                keep = (k0 <= jmmax);
            } else {
                int km0 = k0 % 1023;
                int jdmax = (col0 & 1023) + 127;
                keep = (km0 < jdmax) || (km0 > 991);
            }
            if (keep) kt[c++] = t;
        }
        kt[255] = c;
    }
    __syncthreads();
    const int cnt = kt[255];

    float acc[4][8][4];
#pragma unroll
    for (int mt = 0; mt < 4; mt++)
#pragma unroll
        for (int nt = 0; nt < 8; nt++)
#pragma unroll
            for (int e = 0; e < 4; e++) acc[mt][nt][e] = 0.f;

    auto load_stage = [&](int chunk, int slot) {
        const int k0 = chunk << 5;
        const uint32_t s0 = sb + slot * STG_BYTES;
#pragma unroll
        for (int i = 0; i < 4; i++) {
            int idx = tid + i * NTHR;
            int row = idx >> 2, cc = idx & 3;
            const __half* src = Ah + (size_t)(row0 + row) * K + k0 + cc * 8;
            cp16(s0 + row * 128 + ((cc * 16) ^ ((row & 7) << 4)), src);
        }
#pragma unroll
        for (int i = 0; i < 4; i++) {
            int idx = tid + i * NTHR;
            int row = idx >> 2, cc = idx & 3;
            const __half* src = Bh + (size_t)(col0 + row) * K + k0 + cc * 8;
            cp16(s0 + SA_BYTES + row * 128 + ((cc * 16) ^ ((row & 7) << 4)), src);
        }
    };

    load_stage(kt[0], 0);
    cp_commit();
    if (cnt > 1) load_stage(kt[1], 1);
    cp_commit();

    int rA[4], xA[4];
#pragma unroll
    for (int mt = 0; mt < 4; mt++) {
        int r = wm * 64 + mt * 16 + (lane & 15);
        rA[mt] = r * 128;
        xA[mt] = (r & 7) << 4;
    }
    const int kA2 = (lane >> 4) << 4;
    int rB[4], xB[4];
#pragma unroll
    for (int p = 0; p < 4; p++) {
        int r = wn * 64 + p * 16 + (lane & 7) + ((lane & 16) >> 1);
        rB[p] = r * 128;
        xB[p] = (r & 7) << 4;
    }
    const int kB2 = (lane & 8) << 1;

    for (int i = 0; i < cnt; i++) {
        cp_wait1();
        __syncthreads();
        if (i + 2 < cnt) load_stage(kt[i + 2], (i + 2) % 3);
        cp_commit();

        const uint32_t sA = sb + (i % 3) * STG_BYTES;
        const uint32_t sB = sA + SA_BYTES;
#pragma unroll
        for (int ks = 0; ks < 2; ks++) {
            const int kbA = ks * 32 + kA2;
            const int kbB = ks * 32 + kB2;
            uint32_t Af[4][4], bh[4][4];
#pragma unroll
            for (int mt = 0; mt < 4; mt++)
                ldm_x4(sA + rA[mt] + (kbA ^ xA[mt]), Af[mt]);
#pragma unroll
            for (int p = 0; p < 4; p++)
                ldm_x4(sB + rB[p] + (kbB ^ xB[p]), bh[p]);
#pragma unroll
            for (int mt = 0; mt < 4; mt++)
#pragma unroll
                for (int p = 0; p < 4; p++) {
                    mma16816(acc[mt][2 * p + 0], Af[mt], bh[p]);
                    mma16816(acc[mt][2 * p + 1], Af[mt], bh[p] + 2);
                }
        }
    }

    const int mrow = lane >> 2;
    const int mcol = (lane & 3) * 2;
#pragma unroll
    for (int mt = 0; mt < 4; mt++) {
        const int rbase = row0 + wm * 64 + mt * 16 + mrow;
#pragma unroll
        for (int nt = 0; nt < 8; nt++) {
            const int c = col0 + wn * 64 + nt * 8 + mcol;
            const float b0 = bias[c], b1 = bias[c + 1];
#pragma unroll
            for (int h = 0; h < 2; h++) {
                const int r = rbase + h * 8;
                float v0 = acc[mt][nt][2 * h + 0] + b0;
                float v1 = acc[mt][nt][2 * h + 1] + b1;
                const size_t o = (size_t)r * Nout + c;
                if (MODE == 1) {
                    v0 = fmaxf(v0, 0.f);
                    v1 = fmaxf(v1, 0.f);
                    __half2 ph; ph.x = __float2half(v0); ph.y = __float2half(v1);
                    *(__half2*)(outH + o) = ph;
                } else {
                    *(float2*)(outF + o) = make_float2(v0, v1);
                }
            }
        }
    }
}

// ---------------- finish ----------------
// out[i,j] = z[i,j]*exp(ls[i,inv[j]]) + mu[i,inv[j]]   (zp[i,inv[j]] == z[i,j])
// log_det[i] = sum_j ls[i,inv[j]]
__global__ __launch_bounds__(256) void finish_kernel(
    const float* __restrict__ z, float* __restrict__ out, int Bn, int D)
{
    __shared__ int   sinv[1024];
    __shared__ float red[256];
    const int t = threadIdx.x;
    for (int j = t; j < D; j += 256) sinv[j] = g_inv[j];
    __syncthreads();

#pragma unroll
    for (int r = 0; r < 2; r++) {
        const int i = blockIdx.x * 2 + r;
        const float* resrow = &g_res[(size_t)i * 2 * D];
        const float* zrow   = &z[(size_t)i * D];
        float s = 0.f;
        for (int j = t; j < D; j += 256) {
            int dj   = sinv[j];
            float ls = resrow[D + dj];
            float mu = resrow[dj];
            s += ls;
            out[(size_t)i * D + j] = fmaf(zrow[j], expf(ls), mu);
        }
        red[t] = s;
        __syncthreads();
        for (int off = 128; off > 0; off >>= 1) {
            if (t < off) red[t] += red[t + off];
            __syncthreads();
        }
        if (t == 0) out[(size_t)Bn * D + i] = red[0];
        __syncthreads();
    }
}

// ---------------- launch ----------------
extern "C" void kernel_launch(void* const* d_in, const int* in_sizes, int n_in,
                              void* d_out, int out_size) {
    const float* z    = (const float*)d_in[0];
    const float* W1   = (const float*)d_in[1];
    const float* b1   = (const float*)d_in[2];
    const float* W2   = (const float*)d_in[3];
    const float* b2   = (const float*)d_in[4];
    const int*   perm = (const int*)d_in[5];

    const int D  = in_sizes[5];      // 1024
    const int H  = in_sizes[2];      // 4096
    const int N2 = in_sizes[4];      // 2048
    const int B  = in_sizes[0] / D;  // 4096

    cudaFuncSetAttribute(gemm_mma<1>, cudaFuncAttributeMaxDynamicSharedMemorySize, SM_TOTAL);
    cudaFuncSetAttribute(gemm_mma<2>, cudaFuncAttributeMaxDynamicSharedMemorySize, SM_TOTAL);

    __half *zh, *w1h, *hh, *w2h;
    float* res;
    cudaGetSymbolAddress((void**)&zh,  g_zh);
    cudaGetSymbolAddress((void**)&w1h, g_w1h);
    cudaGetSymbolAddress((void**)&hh,  g_hh);
    cudaGetSymbolAddress((void**)&w2h, g_w2h);
    cudaGetSymbolAddress((void**)&res, g_res);

    split_z_kernel<<<(long)B * D / 256, 256>>>(z, perm, D, (long)B * D);
    const int nblk = (H / 64) * (D / 64) + (N2 / 64) * (H / 64);
    prep_w_all<<<nblk, 256>>>(W1, W2, w1h, w2h, D, H, N2);

    // GEMM1: [B,D] x [D,H]^T-packed -> h (fp16)
    gemm_mma<1><<<dim3(H / 128, B / 128), NTHR, SM_TOTAL>>>(
        zh, w1h, b1, D, H, nullptr, hh);
    // GEMM2: [B,H] x [H,2D]^T-packed -> res (fp32)
    gemm_mma<2><<<dim3(N2 / 128, B / 128), NTHR, SM_TOTAL>>>(
        hh, w2h, b2, H, N2, res, nullptr);

    finish_kernel<<<B / 2, 256>>>(z, (float*)d_out, B, D);
}

// round 17
// speedup vs baseline: 1.7492x; 1.4768x over previous
#include <cuda_runtime.h>
#include <cuda_fp16.h>
#include <cstdint>

// ============================================================
// MADE/IAF flow step on tensor cores via mma.sync (fp16 HMMA, f32 acc).
// Single-pass fp16 (rel_err ~4.4e-4, under the 1e-3 gate).
// + MADE-mask block sparsity (exact k-chunk skipping, ~44%).
// R17: byte-exact resubmission of the R12 best configuration (268.4us)
//      to confirm reproducibility after the unexplained R16 anomaly.
// GEMM1: h = relu(zp @ (W1*M1) + b1)   [4096,1024]x[1024,4096]
// GEMM2: res = h @ (W2*M2) + b2        [4096,4096]x[4096,2048]
// finish: out[i,j] = z[i,j]*exp(ls[i,inv[j]]) + mu[i,inv[j]];
//         log_det[i] = sum_j ls[i,inv[j]]
// ============================================================

// ---------------- device scratch (no allocs allowed) ----------------
__device__ float  g_res[4096ull * 2048ull];   // gemm2 out (fp32)
__device__ int    g_inv[4096];
__device__ __half g_zh[4096ull * 1024ull];    // [B,D] fp16
__device__ __half g_w1h[4096ull * 1024ull];   // [N=4096,K=1024]
__device__ __half g_hh[4096ull * 4096ull];    // [B,H] fp16
__device__ __half g_w2h[2048ull * 4096ull];   // [N=2048,K=4096]

// ---------------- PTX helpers (all baseline sm_80+ PTX) ----------------
__device__ __forceinline__ uint32_t smem_u32(const void* p) {
    uint32_t a;
    asm("{ .reg .u64 t; cvta.to.shared.u64 t, %1; cvt.u32.u64 %0, t; }" : "=r"(a) : "l"(p));
    return a;
}
__device__ __forceinline__ void cp16(uint32_t s, const void* g) {
    asm volatile("cp.async.cg.shared.global [%0], [%1], 16;" :: "r"(s), "l"(g));
}
__device__ __forceinline__ void cp_commit() {
    asm volatile("cp.async.commit_group;" ::: "memory");
}
__device__ __forceinline__ void cp_wait1() {
    asm volatile("cp.async.wait_group 1;" ::: "memory");
}
__device__ __forceinline__ void ldm_x4(uint32_t addr, uint32_t* r) {
    asm volatile("ldmatrix.sync.aligned.m8n8.x4.shared.b16 {%0,%1,%2,%3}, [%4];"
                 : "=r"(r[0]), "=r"(r[1]), "=r"(r[2]), "=r"(r[3]) : "r"(addr));
}
__device__ __forceinline__ void mma16816(float* c, const uint32_t* a, const uint32_t* b) {
    asm volatile(
        "mma.sync.aligned.m16n8k16.row.col.f32.f16.f16.f32 "
        "{%0,%1,%2,%3}, {%4,%5,%6,%7}, {%8,%9}, {%0,%1,%2,%3};"
        : "+f"(c[0]), "+f"(c[1]), "+f"(c[2]), "+f"(c[3])
        : "r"(a[0]), "r"(a[1]), "r"(a[2]), "r"(a[3]), "r"(b[0]), "r"(b[1]));
}

// ---------------- prep kernels ----------------
__global__ void build_inv(const int* __restrict__ perm, int D) {
    int d = blockIdx.x * blockDim.x + threadIdx.x;
    if (d < D) g_inv[perm[d]] = d;
}

__global__ void split_z_kernel(const float* __restrict__ z, const int* __restrict__ perm,
                               int D, long total) {
    long idx = (long)blockIdx.x * blockDim.x + threadIdx.x;
    if (idx >= total) return;
    int i = (int)(idx >> 10);      // D = 1024
    int k = (int)(idx & 1023);
    g_zh[idx] = __float2half(z[(size_t)i * D + perm[k]]);
}

// Merged mask+transpose to fp16 for BOTH weights in one launch.
// W [K,N] fp32 -> out [N,K] fp16, 64x64 tiles.
// mode 1: mask = (n % 1023) >= k          (W1/M1)
// mode 2: mask = (n % 1024) > (k % 1023)  (W2/M2)
__global__ __launch_bounds__(256) void prep_w_all(
    const float* __restrict__ W1, const float* __restrict__ W2,
    __half* __restrict__ o1, __half* __restrict__ o2,
    int D, int H, int N2) {
    __shared__ float tile[64][65];
    const int nblk1 = (H / 64) * (D / 64);
    const int b = blockIdx.x;
    const float* W;
    __half* oH;
    int K, N, mode, tix;
    if (b < nblk1) { W = W1; oH = o1; K = D; N = H;  mode = 1; tix = b; }
    else           { W = W2; oH = o2; K = H; N = N2; mode = 2; tix = b - nblk1; }
    const int nx = N / 64;
    const int n0 = (tix % nx) * 64;
    const int k0 = (tix / nx) * 64;
    const int tid = threadIdx.x;
#pragma unroll
    for (int it = 0; it < 4; it++) {
        int lin = tid + it * 256;
        int k = lin >> 4;
        int n4 = (lin & 15) << 2;
        float4 v = *reinterpret_cast<const float4*>(&W[(size_t)(k0 + k) * N + n0 + n4]);
        tile[k][n4 + 0] = v.x;
        tile[k][n4 + 1] = v.y;
        tile[k][n4 + 2] = v.z;
        tile[k][n4 + 3] = v.w;
    }
    __syncthreads();
    const int tn = tid & 63;
    const int kg = tid >> 6;
    const int n  = n0 + tn;
    const int jm = (mode == 1) ? (n % 1023) : (n & 1023);
    uint32_t hibuf[8];
#pragma unroll
    for (int e = 0; e < 8; e++) {
        float v0, v1;
        {
            int k = k0 + kg * 16 + 2 * e;
            float v = tile[kg * 16 + 2 * e][tn];
            bool m = (mode == 1) ? (jm >= k) : (jm > (k % 1023));
            v0 = m ? v : 0.f;
        }
        {
            int k = k0 + kg * 16 + 2 * e + 1;
            float v = tile[kg * 16 + 2 * e + 1][tn];
            bool m = (mode == 1) ? (jm >= k) : (jm > (k % 1023));
            v1 = m ? v : 0.f;
        }
        __half2 ph; ph.x = __float2half(v0); ph.y = __float2half(v1);
        hibuf[e] = *reinterpret_cast<uint32_t*>(&ph);
    }
    const size_t ob = (size_t)n * K + k0 + kg * 16;
    *reinterpret_cast<uint4*>(oH + ob)     = *reinterpret_cast<uint4*>(hibuf);
    *reinterpret_cast<uint4*>(oH + ob + 8) = *reinterpret_cast<uint4*>(hibuf + 4);
}

// ---------------- mma.sync GEMM (single fp16, chunk skipping) ----------------
// C[m,n] = sum_k A[m,k]*B[n,k]; A [M,K] fp16, B [N,K] fp16.
// CTA tile 128x128, K-chunk 32, 4 warps (2x2), warp tile 64x64, 3-stage cp.async,
// 2 CTAs/SM. Smem rows 128B XOR-swizzled: byte = row*128 + (inner ^ ((row&7)<<4));
// only the k<64-byte (hi) slots of each row are used (A and B identical layout).
#define SA_BYTES   16384
#define STG_BYTES  32768
#define SM_TOTAL   (3 * STG_BYTES + 1024)
#define NTHR       128

template <int MODE>
__global__ __launch_bounds__(NTHR) void gemm_mma(
    const __half* __restrict__ Ah, const __half* __restrict__ Bh,
    const float* __restrict__ bias, int K, int Nout,
    float* __restrict__ outF, __half* __restrict__ outH)
{
    extern __shared__ char smem[];
    const uint32_t sb = smem_u32(smem);
    int* kt = (int*)(smem + 3 * STG_BYTES);
    const int tid  = threadIdx.x;
    const int lane = tid & 31;
    const int w    = tid >> 5;
    const int wm   = w & 1;        // 2 warps in M
    const int wn   = w >> 1;       // 2 warps in N
    const int row0 = blockIdx.y * 128;
    const int col0 = blockIdx.x * 128;
    const int nk   = K >> 5;

    // ---- build kept-chunk list (mask-induced block sparsity) ----
    if (tid == 0) {
        int c = 0;
        for (int t = 0; t < nk; t++) {
            const int k0 = t << 5;
            bool keep;
            if (MODE == 1) {
                int c0 = col0 % 1023;
                int jmmax = (c0 + 127 > 1022) ? 1022 : (c0 + 127);
                keep = (k0 <= jmmax);
            } else {
                int km0 = k0 % 1023;
                int jdmax = (col0 & 1023) + 127;
                keep = (km0 < jdmax) || (km0 > 991);
            }
            if (keep) kt[c++] = t;
        }
        kt[255] = c;
    }
    __syncthreads();
    const int cnt = kt[255];

    float acc[4][8][4];
#pragma unroll
    for (int mt = 0; mt < 4; mt++)
#pragma unroll
        for (int nt = 0; nt < 8; nt++)
#pragma unroll
            for (int e = 0; e < 4; e++) acc[mt][nt][e] = 0.f;

    auto load_stage = [&](int chunk, int slot) {
        const int k0 = chunk << 5;
        const uint32_t s0 = sb + slot * STG_BYTES;
        // A: 128 rows x 64B = 512 cp16
#pragma unroll
        for (int i = 0; i < 4; i++) {
            int idx = tid + i * NTHR;
            int row = idx >> 2, cc = idx & 3;
            const __half* src = Ah + (size_t)(row0 + row) * K + k0 + cc * 8;
            cp16(s0 + row * 128 + ((cc * 16) ^ ((row & 7) << 4)), src);
        }
        // B: 128 rows x 64B = 512 cp16
#pragma unroll
        for (int i = 0; i < 4; i++) {
            int idx = tid + i * NTHR;
            int row = idx >> 2, cc = idx & 3;
            const __half* src = Bh + (size_t)(col0 + row) * K + k0 + cc * 8;
            cp16(s0 + SA_BYTES + row * 128 + ((cc * 16) ^ ((row & 7) << 4)), src);
        }
    };

    load_stage(kt[0], 0);
    cp_commit();
    if (cnt > 1) load_stage(kt[1], 1);
    cp_commit();

    // fragment address components (per-thread constants)
    int rA[4], xA[4];
#pragma unroll
    for (int mt = 0; mt < 4; mt++) {
        int r = wm * 64 + mt * 16 + (lane & 15);
        rA[mt] = r * 128;
        xA[mt] = (r & 7) << 4;
    }
    const int kA2 = (lane >> 4) << 4;          // A k-byte offset part (0 or 16)
    int rB[4], xB[4];
#pragma unroll
    for (int p = 0; p < 4; p++) {
        int r = wn * 64 + p * 16 + (lane & 7) + ((lane & 16) >> 1);
        rB[p] = r * 128;
        xB[p] = (r & 7) << 4;
    }
    const int kB2 = (lane & 8) << 1;           // B k-byte offset part (0 or 16)

    for (int i = 0; i < cnt; i++) {
        cp_wait1();
        __syncthreads();
        if (i + 2 < cnt) load_stage(kt[i + 2], (i + 2) % 3);
        cp_commit();

        const uint32_t sA = sb + (i % 3) * STG_BYTES;
        const uint32_t sB = sA + SA_BYTES;
#pragma unroll
        for (int ks = 0; ks < 2; ks++) {
            const int kbA = ks * 32 + kA2;
            const int kbB = ks * 32 + kB2;
            uint32_t Af[4][4], bh[4][4];
#pragma unroll
            for (int mt = 0; mt < 4; mt++)
                ldm_x4(sA + rA[mt] + (kbA ^ xA[mt]), Af[mt]);
#pragma unroll
            for (int p = 0; p < 4; p++)
                ldm_x4(sB + rB[p] + (kbB ^ xB[p]), bh[p]);
#pragma unroll
            for (int mt = 0; mt < 4; mt++)
#pragma unroll
                for (int p = 0; p < 4; p++) {
                    mma16816(acc[mt][2 * p + 0], Af[mt], bh[p]);
                    mma16816(acc[mt][2 * p + 1], Af[mt], bh[p] + 2);
                }
        }
    }

    // epilogue
    const int mrow = lane >> 2;
    const int mcol = (lane & 3) * 2;
#pragma unroll
    for (int mt = 0; mt < 4; mt++) {
        const int rbase = row0 + wm * 64 + mt * 16 + mrow;
#pragma unroll
        for (int nt = 0; nt < 8; nt++) {
            const int c = col0 + wn * 64 + nt * 8 + mcol;
            const float b0 = bias[c], b1 = bias[c + 1];
#pragma unroll
            for (int h = 0; h < 2; h++) {
                const int r = rbase + h * 8;
                float v0 = acc[mt][nt][2 * h + 0] + b0;
                float v1 = acc[mt][nt][2 * h + 1] + b1;
                const size_t o = (size_t)r * Nout + c;
                if (MODE == 1) {
                    v0 = fmaxf(v0, 0.f);
                    v1 = fmaxf(v1, 0.f);
                    __half2 ph; ph.x = __float2half(v0); ph.y = __float2half(v1);
                    *(__half2*)(outH + o) = ph;
                } else {
                    *(float2*)(outF + o) = make_float2(v0, v1);
                }
            }
        }
    }
}

// ---------------- finish ----------------
// out[i,j] = z[i,j]*exp(ls[i,inv[j]]) + mu[i,inv[j]]   (zp[i,inv[j]] == z[i,j])
// log_det[i] = sum_j ls[i,inv[j]]
__global__ __launch_bounds__(256) void finish_kernel(
    const float* __restrict__ z, float* __restrict__ out, int Bn, int D)
{
    __shared__ int   sinv[1024];
    __shared__ float red[256];
    const int t = threadIdx.x;
    for (int j = t; j < D; j += 256) sinv[j] = g_inv[j];
    __syncthreads();

#pragma unroll
    for (int r = 0; r < 2; r++) {
        const int i = blockIdx.x * 2 + r;
        const float* resrow = &g_res[(size_t)i * 2 * D];
        const float* zrow   = &z[(size_t)i * D];
        float s = 0.f;
        for (int j = t; j < D; j += 256) {
            int dj   = sinv[j];
            float ls = resrow[D + dj];
            float mu = resrow[dj];
            s += ls;
            out[(size_t)i * D + j] = fmaf(zrow[j], expf(ls), mu);
        }
        red[t] = s;
        __syncthreads();
        for (int off = 128; off > 0; off >>= 1) {
            if (t < off) red[t] += red[t + off];
            __syncthreads();
        }
        if (t == 0) out[(size_t)Bn * D + i] = red[0];
        __syncthreads();
    }
}

// ---------------- launch ----------------
extern "C" void kernel_launch(void* const* d_in, const int* in_sizes, int n_in,
                              void* d_out, int out_size) {
    const float* z    = (const float*)d_in[0];
    const float* W1   = (const float*)d_in[1];
    const float* b1   = (const float*)d_in[2];
    const float* W2   = (const float*)d_in[3];
    const float* b2   = (const float*)d_in[4];
    const int*   perm = (const int*)d_in[5];

    const int D  = in_sizes[5];      // 1024
    const int H  = in_sizes[2];      // 4096
    const int N2 = in_sizes[4];      // 2048
    const int B  = in_sizes[0] / D;  // 4096

    cudaFuncSetAttribute(gemm_mma<1>, cudaFuncAttributeMaxDynamicSharedMemorySize, SM_TOTAL);
    cudaFuncSetAttribute(gemm_mma<2>, cudaFuncAttributeMaxDynamicSharedMemorySize, SM_TOTAL);

    __half *zh, *w1h, *hh, *w2h;
    float* res;
    cudaGetSymbolAddress((void**)&zh,  g_zh);
    cudaGetSymbolAddress((void**)&w1h, g_w1h);
    cudaGetSymbolAddress((void**)&hh,  g_hh);
    cudaGetSymbolAddress((void**)&w2h, g_w2h);
    cudaGetSymbolAddress((void**)&res, g_res);

    build_inv<<<(D + 255) / 256, 256>>>(perm, D);
    split_z_kernel<<<(long)B * D / 256, 256>>>(z, perm, D, (long)B * D);
    const int nblk = (H / 64) * (D / 64) + (N2 / 64) * (H / 64);
    prep_w_all<<<nblk, 256>>>(W1, W2, w1h, w2h, D, H, N2);

    // GEMM1: [B,D] x [D,H]^T-packed -> h (fp16)
    gemm_mma<1><<<dim3(H / 128, B / 128), NTHR, SM_TOTAL>>>(
        zh, w1h, b1, D, H, nullptr, hh);
    // GEMM2: [B,H] x [H,2D]^T-packed -> res (fp32)
    gemm_mma<2><<<dim3(N2 / 128, B / 128), NTHR, SM_TOTAL>>>(
        hh, w2h, b2, H, N2, res, nullptr);

    finish_kernel<<<B / 2, 256>>>(z, (float*)d_out, B, D);
}